// round 1
// baseline (speedup 1.0000x reference)
#include <cuda_runtime.h>
#include <cuda_bf16.h>

// Problem dims (fixed by the dataset)
#define NROWS 65536
#define SDIM  128
#define DIN   512
#define HDIM  1024
#define DOUT  256

// Scratch (device globals; no allocation allowed)
__device__ float g_v[NROWS];        // v_i = Uhat_i . w_deep  (incl. b2.w_deep)
__device__ float g_u[HDIM];         // u = W2 @ w_deep
__device__ float g_c;               // c = b2 . w_deep
__device__ float g_G[SDIM * SDIM];  // Gram = X^T X
__device__ float g_t[SDIM];         // t = X^T v
__device__ float g_w[SDIM];         // w = w_struct - G^{-1} t

// ---------------------------------------------------------------------------
// Prep: u = W2 @ w_deep   (1024 rows, dot length 256)
// ---------------------------------------------------------------------------
__global__ void k_u(const float* __restrict__ W2, const float* __restrict__ w_deep) {
    int j = blockIdx.x * blockDim.x + threadIdx.x;  // <<<4,256>>> -> 1024 threads
    const float* r = &W2[(size_t)j * DOUT];
    float s = 0.f;
#pragma unroll 4
    for (int k = 0; k < DOUT; k++) s += r[k] * w_deep[k];
    g_u[j] = s;
}

// c = b2 . w_deep (block reduce)
__global__ void k_c(const float* __restrict__ b2, const float* __restrict__ w_deep) {
    __shared__ float sred[256];
    int tid = threadIdx.x;
    sred[tid] = b2[tid] * w_deep[tid];
    __syncthreads();
    for (int o = 128; o > 0; o >>= 1) {
        if (tid < o) sred[tid] += sred[tid + o];
        __syncthreads();
    }
    if (tid == 0) g_c = sred[0];
}

// zero G, t; init v = c  (must run every launch: graph replay reuses scratch)
__global__ void k_zero_init() {
    int idx = blockIdx.x * blockDim.x + threadIdx.x;
    int stride = gridDim.x * blockDim.x;
    for (int i = idx; i < SDIM * SDIM; i += stride) g_G[i] = 0.f;
    if (idx < SDIM) g_t[idx] = 0.f;
    float c = g_c;
    for (int i = idx; i < NROWS; i += stride) g_v[i] = c;
}

// ---------------------------------------------------------------------------
// Fused MLP GEMM: v_i += sum_j relu(d1_i . W1[:,j] + b1[j]) * u[j]
// Tile: BM=128 x BN=128 x BK=8; 256 threads; 8x8 per thread, FFMA2 packed
// along the N (j) dimension via fma.rn.f32x2.
// ---------------------------------------------------------------------------
#define BM 128
#define BN 128
#define BK 8

__global__ __launch_bounds__(256)
void k_mlp(const float* __restrict__ d1, const float* __restrict__ W1,
           const float* __restrict__ b1) {
    __shared__ float As[BK][BM];   // transposed d1 tile
    __shared__ float Bs[BK][BN];   // W1 tile
    __shared__ float red[BM][17];  // cross-thread row reduction

    const int tid = threadIdx.x;
    const int tx = tid & 15;       // column group (8 cols)
    const int ty = tid >> 4;       // row group (8 rows)
    const int rowBase = blockIdx.y * BM;
    const int colBase = blockIdx.x * BN;

    // accumulators: 8 rows x 4 packed f32x2 pairs (cols tx*8 + 2q, 2q+1)
    unsigned long long acc[8][4];
#pragma unroll
    for (int i = 0; i < 8; i++)
#pragma unroll
        for (int q = 0; q < 4; q++) acc[i][q] = 0ull;

    // prefetch indices (one float4 of A, one float4 of B per thread)
    const int am = tid >> 1, akq = (tid & 1) * 4;
    const int bk = tid >> 5, bn4 = (tid & 31) * 4;

    float4 pa = *(const float4*)&d1[(size_t)(rowBase + am) * DIN + akq];
    float4 pb = *(const float4*)&W1[(size_t)bk * HDIM + colBase + bn4];

    for (int k0 = 0; k0 < DIN; k0 += BK) {
        As[akq + 0][am] = pa.x;
        As[akq + 1][am] = pa.y;
        As[akq + 2][am] = pa.z;
        As[akq + 3][am] = pa.w;
        *(float4*)&Bs[bk][bn4] = pb;
        __syncthreads();

        int kn = k0 + BK;
        if (kn < DIN) {  // prefetch next K-slab under compute
            pa = *(const float4*)&d1[(size_t)(rowBase + am) * DIN + kn + akq];
            pb = *(const float4*)&W1[(size_t)(kn + bk) * HDIM + colBase + bn4];
        }

#pragma unroll
        for (int kk = 0; kk < BK; kk++) {
            float a_s[8];
            *(float4*)&a_s[0] = *(const float4*)&As[kk][ty * 8];
            *(float4*)&a_s[4] = *(const float4*)&As[kk][ty * 8 + 4];
            ulonglong2 b01 = *(const ulonglong2*)&Bs[kk][tx * 8];
            ulonglong2 b23 = *(const ulonglong2*)&Bs[kk][tx * 8 + 4];
            unsigned long long bj[4] = {b01.x, b01.y, b23.x, b23.y};
#pragma unroll
            for (int i = 0; i < 8; i++) {
                unsigned long long a2;
                unsigned int au = __float_as_uint(a_s[i]);
                asm("mov.b64 %0, {%1, %1};" : "=l"(a2) : "r"(au));
#pragma unroll
                for (int q = 0; q < 4; q++)
                    asm("fma.rn.f32x2 %0, %1, %2, %0;"
                        : "+l"(acc[i][q]) : "l"(a2), "l"(bj[q]));
            }
        }
        __syncthreads();
    }

    // epilogue: p_i = sum_j relu(h_ij + b1_j) * u_j  over this block's 8 cols
    float bu[8], bb[8];
#pragma unroll
    for (int j = 0; j < 8; j++) {
        int c = colBase + tx * 8 + j;
        bu[j] = g_u[c];
        bb[j] = b1[c];
    }
#pragma unroll
    for (int i = 0; i < 8; i++) {
        float p = 0.f;
#pragma unroll
        for (int q = 0; q < 4; q++) {
            float lo = __uint_as_float((unsigned)(acc[i][q] & 0xffffffffu));
            float hi = __uint_as_float((unsigned)(acc[i][q] >> 32));
            p += fmaxf(lo + bb[2 * q], 0.f) * bu[2 * q];
            p += fmaxf(hi + bb[2 * q + 1], 0.f) * bu[2 * q + 1];
        }
        red[ty * 8 + i][tx] = p;
    }
    __syncthreads();
    if (tid < BM) {
        float s = 0.f;
#pragma unroll
        for (int x = 0; x < 16; x++) s += red[tid][x];
        atomicAdd(&g_v[rowBase + tid], s);
    }
}

// ---------------------------------------------------------------------------
// Gram: G += X^T X and t += X^T v  (per-block partials + atomics)
// ---------------------------------------------------------------------------
__global__ __launch_bounds__(256)
void k_gram(const float* __restrict__ X) {
    __shared__ float xs[64][SDIM];
    __shared__ float vs[64];
    const int tid = threadIdx.x;
    const int i0 = (tid & 15) * 8, j0 = (tid >> 4) * 8;
    float acc[8][8] = {};
    float tpart = 0.f;
    const int base = blockIdx.x * 512;  // <<<128,256>>>: each block 512 rows

    for (int c = 0; c < 512; c += 64) {
#pragma unroll
        for (int l = 0; l < 8; l++) {
            int idx = tid + l * 256;             // float4 index in [0,2048)
            int r = idx >> 5, c4 = (idx & 31) * 4;
            *(float4*)&xs[r][c4] =
                *(const float4*)&X[(size_t)(base + c + r) * SDIM + c4];
        }
        if (tid < 64) vs[tid] = g_v[base + c + tid];
        __syncthreads();

        for (int k = 0; k < 64; k++) {
            float a[8], b[8];
            *(float4*)&a[0] = *(const float4*)&xs[k][i0];
            *(float4*)&a[4] = *(const float4*)&xs[k][i0 + 4];
            *(float4*)&b[0] = *(const float4*)&xs[k][j0];
            *(float4*)&b[4] = *(const float4*)&xs[k][j0 + 4];
#pragma unroll
            for (int i = 0; i < 8; i++)
#pragma unroll
                for (int j = 0; j < 8; j++) acc[i][j] += a[i] * b[j];
        }
        if (tid < SDIM) {
            float tp = 0.f;
            for (int k = 0; k < 64; k++) tp += vs[k] * xs[k][tid];
            tpart += tp;
        }
        __syncthreads();
    }
#pragma unroll
    for (int i = 0; i < 8; i++)
#pragma unroll
        for (int j = 0; j < 8; j++)
            atomicAdd(&g_G[(i0 + i) * SDIM + (j0 + j)], acc[i][j]);
    if (tid < SDIM) atomicAdd(&g_t[tid], tpart);
}

// ---------------------------------------------------------------------------
// Solve G y = t by Jacobi (G ~ N*(I + E), ||E|| ~ 0.09 -> 25 iters = exact),
// then w = w_struct - y.
// ---------------------------------------------------------------------------
__global__ void k_solve(const float* __restrict__ w_struct) {
    __shared__ float y[SDIM];
    __shared__ float tt[SDIM];
    int tid = threadIdx.x;  // 128 threads
    float dinv = 1.f / g_G[tid * SDIM + tid];
    tt[tid] = g_t[tid];
    y[tid] = tt[tid] * dinv;
    __syncthreads();
    for (int it = 0; it < 25; it++) {
        float s = 0.f;
#pragma unroll 8
        for (int m = 0; m < SDIM; m++) s += g_G[tid * SDIM + m] * y[m];
        float yn = y[tid] + (tt[tid] - s) * dinv;
        __syncthreads();
        y[tid] = yn;
        __syncthreads();
    }
    g_w[tid] = w_struct[tid] - y[tid];
}

// ---------------------------------------------------------------------------
// Final: out_i = v_i + X_i . w   (warp per row, memory-bound)
// ---------------------------------------------------------------------------
__global__ __launch_bounds__(256)
void k_final(const float* __restrict__ X, float* __restrict__ out) {
    __shared__ float sw[SDIM];
    int tid = threadIdx.x;
    if (tid < SDIM) sw[tid] = g_w[tid];
    __syncthreads();
    int lane = tid & 31;
    int warp = (blockIdx.x * blockDim.x + tid) >> 5;
    int nwarps = (gridDim.x * blockDim.x) >> 5;
    for (int row = warp; row < NROWS; row += nwarps) {
        const float* xr = &X[(size_t)row * SDIM];
        float s = xr[lane] * sw[lane] + xr[lane + 32] * sw[lane + 32] +
                  xr[lane + 64] * sw[lane + 64] + xr[lane + 96] * sw[lane + 96];
#pragma unroll
        for (int o = 16; o > 0; o >>= 1) s += __shfl_down_sync(0xffffffffu, s, o);
        if (lane == 0) out[row] = g_v[row] + s;
    }
}

// ---------------------------------------------------------------------------
extern "C" void kernel_launch(void* const* d_in, const int* in_sizes, int n_in,
                              void* d_out, int out_size) {
    const float* X        = (const float*)d_in[0];  // structured [N,128]
    const float* d1       = (const float*)d_in[1];  // [N,512]
    const float* W1       = (const float*)d_in[2];  // [512,1024]
    const float* b1       = (const float*)d_in[3];  // [1024]
    const float* W2       = (const float*)d_in[4];  // [1024,256]
    const float* b2       = (const float*)d_in[5];  // [256]
    const float* w_struct = (const float*)d_in[6];  // [128,1]
    const float* w_deep   = (const float*)d_in[7];  // [256,1]
    float* out = (float*)d_out;

    k_u<<<4, 256>>>(W2, w_deep);
    k_c<<<1, 256>>>(b2, w_deep);
    k_zero_init<<<128, 256>>>();
    k_mlp<<<dim3(HDIM / BN, NROWS / BM), 256>>>(d1, W1, b1);
    k_gram<<<128, 256>>>(X);
    k_solve<<<1, SDIM>>>(w_struct);
    k_final<<<1024, 256>>>(X, out);
}

// round 6
// speedup vs baseline: 1.1634x; 1.1634x over previous
#include <cuda_runtime.h>
#include <cuda_bf16.h>
#include <cstdint>

// Problem dims (fixed by the dataset)
#define NROWS 65536
#define SDIM  128
#define DIN   512
#define HDIM  1024
#define DOUT  256

// ---------------------------------------------------------------------------
// Scratch (device globals; no allocation allowed)
// ---------------------------------------------------------------------------
__device__ float g_v[NROWS];        // v_i = Uhat_i . w_deep  (incl. b2.w_deep)
__device__ float g_u[HDIM];         // u = W2 @ w_deep
__device__ float g_c;               // c = b2 . w_deep
__device__ float g_G[SDIM * SDIM];  // Gram = X^T X
__device__ float g_t[SDIM];         // t = X^T v
__device__ float g_w[SDIM];         // w = w_struct - G^{-1} t

// bf16 hi/lo split copies for tensor-core GEMM
__device__ __align__(16) __nv_bfloat16 g_d1hi[(size_t)NROWS * DIN];  // 64MB
__device__ __align__(16) __nv_bfloat16 g_d1lo[(size_t)NROWS * DIN];  // 64MB
__device__ __align__(16) __nv_bfloat16 g_W1thi[HDIM * DIN];          // B^T [N,K]
__device__ __align__(16) __nv_bfloat16 g_W1tlo[HDIM * DIN];

// ---------------------------------------------------------------------------
// Helpers
// ---------------------------------------------------------------------------
__device__ __forceinline__ uint32_t smem_u32(const void* p) {
    uint32_t a;
    asm("{ .reg .u64 t; cvta.to.shared.u64 t, %1; cvt.u32.u64 %0, t; }"
        : "=r"(a) : "l"(p));
    return a;
}

#define CP16(sa, ga) \
    asm volatile("cp.async.cg.shared.global [%0], [%1], 16;" ::"r"(sa), "l"(ga) : "memory")
#define CP_COMMIT() asm volatile("cp.async.commit_group;" ::: "memory")
#define CP_WAIT1() asm volatile("cp.async.wait_group 1;" ::: "memory")

// m16n8k16 row.col bf16 MMA, fp32 accum (sm_80+ baseline -> legal on sm_103)
#define MMA4(d, a0, a1, a2, a3, b0, b1)                                     \
    asm volatile(                                                           \
        "mma.sync.aligned.m16n8k16.row.col.f32.bf16.bf16.f32 "              \
        "{%0,%1,%2,%3}, {%4,%5,%6,%7}, {%8,%9}, {%0,%1,%2,%3};"             \
        : "+f"((d)[0]), "+f"((d)[1]), "+f"((d)[2]), "+f"((d)[3])            \
        : "r"(a0), "r"(a1), "r"(a2), "r"(a3), "r"(b0), "r"(b1))

// ---------------------------------------------------------------------------
// Prep: u = W2 @ w_deep
// ---------------------------------------------------------------------------
__global__ void k_u(const float* __restrict__ W2, const float* __restrict__ w_deep) {
    int j = blockIdx.x * blockDim.x + threadIdx.x;
    const float* r = &W2[(size_t)j * DOUT];
    float s = 0.f;
#pragma unroll 4
    for (int k = 0; k < DOUT; k++) s += r[k] * w_deep[k];
    g_u[j] = s;
}

__global__ void k_c(const float* __restrict__ b2, const float* __restrict__ w_deep) {
    __shared__ float sred[256];
    int tid = threadIdx.x;
    sred[tid] = b2[tid] * w_deep[tid];
    __syncthreads();
    for (int o = 128; o > 0; o >>= 1) {
        if (tid < o) sred[tid] += sred[tid + o];
        __syncthreads();
    }
    if (tid == 0) g_c = sred[0];
}

// zero G, t; init v = c  (runs every launch: graph replay reuses scratch)
__global__ void k_zero_init() {
    int idx = blockIdx.x * blockDim.x + threadIdx.x;
    int stride = gridDim.x * blockDim.x;
    for (int i = idx; i < SDIM * SDIM; i += stride) g_G[i] = 0.f;
    if (idx < SDIM) g_t[idx] = 0.f;
    float c = g_c;
    for (int i = idx; i < NROWS; i += stride) g_v[i] = c;
}

// ---------------------------------------------------------------------------
// bf16 hi/lo split conversions
// ---------------------------------------------------------------------------
__global__ void k_conv_d1(const float4* __restrict__ in) {
    int i = blockIdx.x * blockDim.x + threadIdx.x;
    int stride = gridDim.x * blockDim.x;
    uint2* oh = reinterpret_cast<uint2*>(g_d1hi);
    uint2* ol = reinterpret_cast<uint2*>(g_d1lo);
    for (; i < NROWS * DIN / 4; i += stride) {
        float4 v = in[i];
        float x[4] = {v.x, v.y, v.z, v.w};
        unsigned hs[4], ls[4];
#pragma unroll
        for (int q = 0; q < 4; q++) {
            __nv_bfloat16 h = __float2bfloat16(x[q]);
            __nv_bfloat16 l = __float2bfloat16(x[q] - __bfloat162float(h));
            hs[q] = __bfloat16_as_ushort(h);
            ls[q] = __bfloat16_as_ushort(l);
        }
        oh[i] = make_uint2(hs[0] | (hs[1] << 16), hs[2] | (hs[3] << 16));
        ol[i] = make_uint2(ls[0] | (ls[1] << 16), ls[2] | (ls[3] << 16));
    }
}

// W1 [DIN, HDIM] -> transposed bf16 hi/lo [HDIM, DIN]
__global__ void k_conv_w1(const float* __restrict__ W1) {
    int i = blockIdx.x * blockDim.x + threadIdx.x;  // <<<2048,256>>> exact
    int k = i >> 10, n = i & (HDIM - 1);
    float x = W1[i];
    __nv_bfloat16 h = __float2bfloat16(x);
    __nv_bfloat16 l = __float2bfloat16(x - __bfloat162float(h));
    g_W1thi[n * DIN + k] = h;
    g_W1tlo[n * DIN + k] = l;
}

// ---------------------------------------------------------------------------
// Tensor-core fused MLP via mma.sync (HMMA):
//   v_i += sum_j relu((d1 @ W1)_ij + b1_j) * u_j
// C tile 128x128 per CTA (8 warps, each 32x64). K chunks of 32, 3-stage
// cp.async pipeline. 3-term bf16 hi/lo fp32 emulation.
// Smem row layout per tile row: [hi 64B][lo 64B][pad 16B] = 144B
//   -> fragment LDS loads bank-conflict-free (row*36+tg distinct mod 32).
// ---------------------------------------------------------------------------
#define BKC     32
#define ROWB    144                     // padded row bytes
#define TILEB2  (128 * ROWB)            // 18432 B (one operand, one stage)
#define STAGEB  (2 * TILEB2)            // A + B per stage
#define NSTG    3
#define SMEM_MMA (1024 + NSTG * STAGEB) // 111616 B

__global__ __launch_bounds__(256, 2) void k_mlp_mma(const float* __restrict__ b1) {
    extern __shared__ char sm[];
    float* bs = (float*)sm;            // [128] b1 slice
    float* us = (float*)(sm + 512);    // [128] u slice
    char* tiles = sm + 1024;

    const int tid = threadIdx.x, lane = tid & 31, wid = tid >> 5;
    const int wm = wid & 3, wn = wid >> 2;      // warp tile: rows wm*32, cols wn*64
    const int g = lane >> 2, tg = lane & 3;
    const int rowBase = blockIdx.y * 128, colBase = blockIdx.x * 128;

    if (tid < 128) {
        bs[tid] = b1[colBase + tid];
        us[tid] = g_u[colBase + tid];
    }

    const __nv_bfloat16* Ah = g_d1hi + (size_t)rowBase * DIN;
    const __nv_bfloat16* Al = g_d1lo + (size_t)rowBase * DIN;
    const __nv_bfloat16* Bh = g_W1thi + (size_t)colBase * DIN;
    const __nv_bfloat16* Bl = g_W1tlo + (size_t)colBase * DIN;

    const uint32_t tilesU = smem_u32(tiles);

    float acc[2][8][4] = {};  // [mtile][ntile][frag]

    auto load_stage = [&](int buf, int k0) {
        uint32_t sa = tilesU + buf * STAGEB;
        uint32_t sb = sa + TILEB2;
#pragma unroll
        for (int l = 0; l < 4; l++) {
            int idx = tid + l * 256;          // 0..1023
            int r = idx >> 3;                 // tile row 0..127
            int t = (idx >> 2) & 1;           // 0=hi 1=lo
            int s = idx & 3;                  // 16B segment (8 elems)
            uint32_t so = (uint32_t)(r * ROWB + t * 64 + s * 16);
            size_t go = (size_t)r * DIN + k0 + s * 8;
            CP16(sa + so, (t ? Al : Ah) + go);
            CP16(sb + so, (t ? Bl : Bh) + go);
        }
    };

    auto compute_stage = [&](int buf) {
        const char* SA = tiles + buf * STAGEB;
        const char* SB = SA + TILEB2;
#pragma unroll
        for (int kk = 0; kk < 2; kk++) {      // two k16 steps per BK=32 chunk
            int kb = kk * 32;                 // byte offset: 16 elems * 2B
            uint32_t a[2][2][4];
#pragma unroll
            for (int mt = 0; mt < 2; mt++) {
                int r0 = wm * 32 + mt * 16 + g;
#pragma unroll
                for (int t = 0; t < 2; t++) {
                    const char* base = SA + t * 64 + kb + tg * 4;
                    a[mt][t][0] = *(const uint32_t*)(base + (size_t)r0 * ROWB);
                    a[mt][t][1] = *(const uint32_t*)(base + (size_t)(r0 + 8) * ROWB);
                    a[mt][t][2] = *(const uint32_t*)(base + (size_t)r0 * ROWB + 16);
                    a[mt][t][3] = *(const uint32_t*)(base + (size_t)(r0 + 8) * ROWB + 16);
                }
            }
#pragma unroll
            for (int nt = 0; nt < 8; nt++) {
                int n = wn * 64 + nt * 8 + g;
                const char* bb = SB + (size_t)n * ROWB + kb + tg * 4;
                uint32_t bh0 = *(const uint32_t*)(bb);
                uint32_t bh1 = *(const uint32_t*)(bb + 16);
                uint32_t bl0 = *(const uint32_t*)(bb + 64);
                uint32_t bl1 = *(const uint32_t*)(bb + 64 + 16);
#pragma unroll
                for (int mt = 0; mt < 2; mt++) {
                    MMA4(acc[mt][nt], a[mt][0][0], a[mt][0][1], a[mt][0][2], a[mt][0][3], bh0, bh1);
                    MMA4(acc[mt][nt], a[mt][0][0], a[mt][0][1], a[mt][0][2], a[mt][0][3], bl0, bl1);
                    MMA4(acc[mt][nt], a[mt][1][0], a[mt][1][1], a[mt][1][2], a[mt][1][3], bh0, bh1);
                }
            }
        }
    };

    load_stage(0, 0);
    CP_COMMIT();
    load_stage(1, BKC);
    CP_COMMIT();

#pragma unroll 1
    for (int c = 0; c < DIN / BKC; c++) {   // 16 chunks
        CP_WAIT1();
        __syncthreads();
        compute_stage(c % NSTG);
        __syncthreads();
        if (c + 2 < DIN / BKC) load_stage((c + 2) % NSTG, (c + 2) * BKC);
        CP_COMMIT();
    }

    // Epilogue: p(row) = sum_cols relu(acc + b1)*u, reduce quad, atomic to g_v
#pragma unroll
    for (int mt = 0; mt < 2; mt++) {
#pragma unroll
        for (int h = 0; h < 2; h++) {
            float p = 0.f;
#pragma unroll
            for (int nt = 0; nt < 8; nt++) {
                int c0 = wn * 64 + nt * 8 + tg * 2;
                p += fmaxf(acc[mt][nt][h * 2 + 0] + bs[c0], 0.f) * us[c0];
                p += fmaxf(acc[mt][nt][h * 2 + 1] + bs[c0 + 1], 0.f) * us[c0 + 1];
            }
            p += __shfl_xor_sync(0xffffffffu, p, 1);
            p += __shfl_xor_sync(0xffffffffu, p, 2);
            if (tg == 0)
                atomicAdd(&g_v[rowBase + wm * 32 + mt * 16 + h * 8 + g], p);
        }
    }
}

// ---------------------------------------------------------------------------
// Gram: G += X^T X and t += X^T v  (per-block partials + atomics) [R1-proven]
// ---------------------------------------------------------------------------
__global__ __launch_bounds__(256)
void k_gram(const float* __restrict__ X) {
    __shared__ float xs[64][SDIM];
    __shared__ float vs[64];
    const int tid = threadIdx.x;
    const int i0 = (tid & 15) * 8, j0 = (tid >> 4) * 8;
    float acc[8][8] = {};
    float tpart = 0.f;
    const int base = blockIdx.x * 256;  // <<<256,256>>>: 256 rows per block

    for (int c = 0; c < 256; c += 64) {
#pragma unroll
        for (int l = 0; l < 8; l++) {
            int idx = tid + l * 256;
            int r = idx >> 5, c4 = (idx & 31) * 4;
            *(float4*)&xs[r][c4] =
                *(const float4*)&X[(size_t)(base + c + r) * SDIM + c4];
        }
        if (tid < 64) vs[tid] = g_v[base + c + tid];
        __syncthreads();

        for (int k = 0; k < 64; k++) {
            float a[8], b[8];
            *(float4*)&a[0] = *(const float4*)&xs[k][i0];
            *(float4*)&a[4] = *(const float4*)&xs[k][i0 + 4];
            *(float4*)&b[0] = *(const float4*)&xs[k][j0];
            *(float4*)&b[4] = *(const float4*)&xs[k][j0 + 4];
#pragma unroll
            for (int i = 0; i < 8; i++)
#pragma unroll
                for (int j = 0; j < 8; j++) acc[i][j] += a[i] * b[j];
        }
        if (tid < SDIM) {
            float tp = 0.f;
            for (int k = 0; k < 64; k++) tp += vs[k] * xs[k][tid];
            tpart += tp;
        }
        __syncthreads();
    }
#pragma unroll
    for (int i = 0; i < 8; i++)
#pragma unroll
        for (int j = 0; j < 8; j++)
            atomicAdd(&g_G[(i0 + i) * SDIM + (j0 + j)], acc[i][j]);
    if (tid < SDIM) atomicAdd(&g_t[tid], tpart);
}

// ---------------------------------------------------------------------------
// Solve G y = t by Jacobi (25 iters), then w = w_struct - y.
// ---------------------------------------------------------------------------
__global__ void k_solve(const float* __restrict__ w_struct) {
    __shared__ float y[SDIM];
    __shared__ float tt[SDIM];
    int tid = threadIdx.x;  // 128 threads
    float dinv = 1.f / g_G[tid * SDIM + tid];
    tt[tid] = g_t[tid];
    y[tid] = tt[tid] * dinv;
    __syncthreads();
    for (int it = 0; it < 25; it++) {
        float s = 0.f;
#pragma unroll 8
        for (int m = 0; m < SDIM; m++) s += g_G[tid * SDIM + m] * y[m];
        float yn = y[tid] + (tt[tid] - s) * dinv;
        __syncthreads();
        y[tid] = yn;
        __syncthreads();
    }
    g_w[tid] = w_struct[tid] - y[tid];
}

// ---------------------------------------------------------------------------
// Final: out_i = v_i + X_i . w
// ---------------------------------------------------------------------------
__global__ __launch_bounds__(256)
void k_final(const float* __restrict__ X, float* __restrict__ out) {
    __shared__ float sw[SDIM];
    int tid = threadIdx.x;
    if (tid < SDIM) sw[tid] = g_w[tid];
    __syncthreads();
    int lane = tid & 31;
    int warp = (blockIdx.x * blockDim.x + tid) >> 5;
    int nwarps = (gridDim.x * blockDim.x) >> 5;
    for (int row = warp; row < NROWS; row += nwarps) {
        const float* xr = &X[(size_t)row * SDIM];
        float s = xr[lane] * sw[lane] + xr[lane + 32] * sw[lane + 32] +
                  xr[lane + 64] * sw[lane + 64] + xr[lane + 96] * sw[lane + 96];
#pragma unroll
        for (int o = 16; o > 0; o >>= 1) s += __shfl_down_sync(0xffffffffu, s, o);
        if (lane == 0) out[row] = g_v[row] + s;
    }
}

// ---------------------------------------------------------------------------
extern "C" void kernel_launch(void* const* d_in, const int* in_sizes, int n_in,
                              void* d_out, int out_size) {
    const float* X        = (const float*)d_in[0];  // structured [N,128]
    const float* d1       = (const float*)d_in[1];  // [N,512]
    const float* W1       = (const float*)d_in[2];  // [512,1024]
    const float* b1       = (const float*)d_in[3];  // [1024]
    const float* W2       = (const float*)d_in[4];  // [1024,256]
    const float* b2       = (const float*)d_in[5];  // [256]
    const float* w_struct = (const float*)d_in[6];  // [128,1]
    const float* w_deep   = (const float*)d_in[7];  // [256,1]
    float* out = (float*)d_out;

    cudaFuncSetAttribute(k_mlp_mma, cudaFuncAttributeMaxDynamicSharedMemorySize,
                         SMEM_MMA);

    k_u<<<4, 256>>>(W2, w_deep);
    k_c<<<1, 256>>>(b2, w_deep);
    k_zero_init<<<128, 256>>>();
    k_conv_d1<<<4096, 256>>>((const float4*)d1);
    k_conv_w1<<<2048, 256>>>(W1);
    k_mlp_mma<<<dim3(HDIM / 128, NROWS / 128), 256, SMEM_MMA>>>(b1);
    k_gram<<<256, 256>>>(X);
    k_solve<<<1, SDIM>>>(w_struct);
    k_final<<<1024, 256>>>(X, out);
}

// round 10
// speedup vs baseline: 1.8727x; 1.6098x over previous
#include <cuda_runtime.h>
#include <cuda_bf16.h>
#include <cstdint>

// Problem dims (fixed by the dataset)
#define NROWS 65536
#define SDIM  128
#define DIN   512
#define HDIM  1024
#define DOUT  256

// ---------------------------------------------------------------------------
// Scratch (device globals; no allocation allowed)
// ---------------------------------------------------------------------------
__device__ float g_v[NROWS];        // v_i = Uhat_i . w_deep  (incl. b2.w_deep)
__device__ float g_u[HDIM];         // u = W2 @ w_deep
__device__ float g_c;               // c = b2 . w_deep
__device__ float g_G[SDIM * SDIM];  // Gram = X^T X
__device__ float g_t[SDIM];         // t = X^T v
__device__ float g_w[SDIM];         // w = w_struct - G^{-1} t

// bf16 hi/lo split copies for tensor-core GEMM
__device__ __align__(16) __nv_bfloat16 g_d1hi[(size_t)NROWS * DIN];  // 64MB
__device__ __align__(16) __nv_bfloat16 g_d1lo[(size_t)NROWS * DIN];  // 64MB
__device__ __align__(16) __nv_bfloat16 g_W1thi[HDIM * DIN];          // B^T [N,K]
__device__ __align__(16) __nv_bfloat16 g_W1tlo[HDIM * DIN];

// ---------------------------------------------------------------------------
// Helpers
// ---------------------------------------------------------------------------
__device__ __forceinline__ uint32_t smem_u32(const void* p) {
    uint32_t a;
    asm("{ .reg .u64 t; cvta.to.shared.u64 t, %1; cvt.u32.u64 %0, t; }"
        : "=r"(a) : "l"(p));
    return a;
}

#define CP16(sa, ga) \
    asm volatile("cp.async.cg.shared.global [%0], [%1], 16;" ::"r"(sa), "l"(ga) : "memory")
#define CP_COMMIT() asm volatile("cp.async.commit_group;" ::: "memory")
#define CP_WAIT1() asm volatile("cp.async.wait_group 1;" ::: "memory")

// m16n8k16 row.col bf16 MMA, fp32 accum (sm_80+ baseline -> legal on sm_103)
#define MMA4(d, a0, a1, a2, a3, b0, b1)                                     \
    asm volatile(                                                           \
        "mma.sync.aligned.m16n8k16.row.col.f32.bf16.bf16.f32 "              \
        "{%0,%1,%2,%3}, {%4,%5,%6,%7}, {%8,%9}, {%0,%1,%2,%3};"             \
        : "+f"((d)[0]), "+f"((d)[1]), "+f"((d)[2]), "+f"((d)[3])            \
        : "r"(a0), "r"(a1), "r"(a2), "r"(a3), "r"(b0), "r"(b1))

// ldmatrix x4 (sm_75+): 4 8x8 b16 tiles, per-lane row addresses
#define LDSM4(r, a)                                                         \
    asm volatile(                                                           \
        "ldmatrix.sync.aligned.m8n8.x4.shared.b16 {%0,%1,%2,%3}, [%4];"     \
        : "=r"((r)[0]), "=r"((r)[1]), "=r"((r)[2]), "=r"((r)[3])            \
        : "r"(a))

// ---------------------------------------------------------------------------
// Prep: u = W2 @ w_deep
// ---------------------------------------------------------------------------
__global__ void k_u(const float* __restrict__ W2, const float* __restrict__ w_deep) {
    int j = blockIdx.x * blockDim.x + threadIdx.x;
    const float* r = &W2[(size_t)j * DOUT];
    float s = 0.f;
#pragma unroll 4
    for (int k = 0; k < DOUT; k++) s += r[k] * w_deep[k];
    g_u[j] = s;
}

__global__ void k_c(const float* __restrict__ b2, const float* __restrict__ w_deep) {
    __shared__ float sred[256];
    int tid = threadIdx.x;
    sred[tid] = b2[tid] * w_deep[tid];
    __syncthreads();
    for (int o = 128; o > 0; o >>= 1) {
        if (tid < o) sred[tid] += sred[tid + o];
        __syncthreads();
    }
    if (tid == 0) g_c = sred[0];
}

// zero G, t; init v = c  (runs every launch: graph replay reuses scratch)
__global__ void k_zero_init() {
    int idx = blockIdx.x * blockDim.x + threadIdx.x;
    int stride = gridDim.x * blockDim.x;
    for (int i = idx; i < SDIM * SDIM; i += stride) g_G[i] = 0.f;
    if (idx < SDIM) g_t[idx] = 0.f;
    float c = g_c;
    for (int i = idx; i < NROWS; i += stride) g_v[i] = c;
}

// ---------------------------------------------------------------------------
// bf16 hi/lo split conversions
// ---------------------------------------------------------------------------
__global__ void k_conv_d1(const float4* __restrict__ in) {
    int i = blockIdx.x * blockDim.x + threadIdx.x;
    int stride = gridDim.x * blockDim.x;
    uint2* oh = reinterpret_cast<uint2*>(g_d1hi);
    uint2* ol = reinterpret_cast<uint2*>(g_d1lo);
    for (; i < NROWS * DIN / 4; i += stride) {
        float4 v = in[i];
        float x[4] = {v.x, v.y, v.z, v.w};
        unsigned hs[4], ls[4];
#pragma unroll
        for (int q = 0; q < 4; q++) {
            __nv_bfloat16 h = __float2bfloat16(x[q]);
            __nv_bfloat16 l = __float2bfloat16(x[q] - __bfloat162float(h));
            hs[q] = __bfloat16_as_ushort(h);
            ls[q] = __bfloat16_as_ushort(l);
        }
        oh[i] = make_uint2(hs[0] | (hs[1] << 16), hs[2] | (hs[3] << 16));
        ol[i] = make_uint2(ls[0] | (ls[1] << 16), ls[2] | (ls[3] << 16));
    }
}

// W1 [DIN, HDIM] -> transposed bf16 hi/lo [HDIM, DIN]
__global__ void k_conv_w1(const float* __restrict__ W1) {
    int i = blockIdx.x * blockDim.x + threadIdx.x;  // <<<2048,256>>> exact
    int k = i >> 10, n = i & (HDIM - 1);
    float x = W1[i];
    __nv_bfloat16 h = __float2bfloat16(x);
    __nv_bfloat16 l = __float2bfloat16(x - __bfloat162float(h));
    g_W1thi[n * DIN + k] = h;
    g_W1tlo[n * DIN + k] = l;
}

// ---------------------------------------------------------------------------
// Tensor-core fused MLP via mma.sync (HMMA):
//   v_i += sum_j relu((d1 @ W1)_ij + b1_j) * u_j
// C tile 128x128 per CTA (8 warps, each 32x64). K chunks of 32, 3-stage
// cp.async pipeline, ONE barrier per chunk. ldmatrix.x4 fragment loads.
// 3-term bf16 hi/lo fp32 emulation.
// Smem row layout per tile row: [hi 64B][lo 64B][pad 16B] = 144B
//   -> ldmatrix rows land on banks 4*r (distinct), conflict-free.
// ---------------------------------------------------------------------------
#define BKC     32
#define ROWB    144                     // padded row bytes
#define TILEB2  (128 * ROWB)            // 18432 B (one operand, one stage)
#define STAGEB  (2 * TILEB2)            // A + B per stage
#define NSTG    3
#define SMEM_MMA (1024 + NSTG * STAGEB) // 111616 B

__global__ __launch_bounds__(256, 2) void k_mlp_mma(const float* __restrict__ b1) {
    extern __shared__ char sm[];
    float* bs = (float*)sm;            // [128] b1 slice
    float* us = (float*)(sm + 512);    // [128] u slice
    char* tiles = sm + 1024;

    const int tid = threadIdx.x, lane = tid & 31, wid = tid >> 5;
    const int wm = wid & 3, wn = wid >> 2;      // warp tile: rows wm*32, cols wn*64
    const int g = lane >> 2, tg = lane & 3;
    const int rowBase = blockIdx.y * 128, colBase = blockIdx.x * 128;

    if (tid < 128) {
        bs[tid] = b1[colBase + tid];
        us[tid] = g_u[colBase + tid];
    }

    const __nv_bfloat16* Ah = g_d1hi + (size_t)rowBase * DIN;
    const __nv_bfloat16* Al = g_d1lo + (size_t)rowBase * DIN;
    const __nv_bfloat16* Bh = g_W1thi + (size_t)colBase * DIN;
    const __nv_bfloat16* Bl = g_W1tlo + (size_t)colBase * DIN;

    const uint32_t tilesU = smem_u32(tiles);

    // --- ldmatrix per-lane address offsets (within a stage buffer) ---
    // A tiles (x4): mat0 rows0-7/kseg0, mat1 rows8-15/kseg0, mat2 rows0-7/kseg1,
    //               mat3 rows8-15/kseg1  -> regs = a0,a1,a2,a3 of m16n8k16 A frag.
    // B tiles (x4): mat0 n0-7/kseg0, mat1 n0-7/kseg1, mat2 n8-15/kseg0,
    //               mat3 n8-15/kseg1    -> regs = b0,b1 (nt), b0,b1 (nt+1).
    const int mrow = lane & 7, mat = lane >> 3;
    uint32_t aoff[2][2];  // [mt][t]
#pragma unroll
    for (int mt = 0; mt < 2; mt++)
#pragma unroll
        for (int t = 0; t < 2; t++) {
            int r = wm * 32 + mt * 16 + (mat & 1) * 8 + mrow;
            aoff[mt][t] = (uint32_t)(r * ROWB + t * 64 + (mat >> 1) * 16);
        }
    uint32_t boff[4];  // [ntp] (t added at use: +0 hi, +64 lo)
#pragma unroll
    for (int ntp = 0; ntp < 4; ntp++) {
        int n = wn * 64 + ntp * 16 + (mat >> 1) * 8 + mrow;
        boff[ntp] = (uint32_t)(TILEB2 + n * ROWB + (mat & 1) * 16);
    }

    float acc[2][8][4] = {};  // [mtile][ntile][frag]

    auto load_stage = [&](int buf, int k0) {
        uint32_t sa = tilesU + buf * STAGEB;
        uint32_t sb = sa + TILEB2;
#pragma unroll
        for (int l = 0; l < 4; l++) {
            int idx = tid + l * 256;          // 0..1023
            int r = idx >> 3;                 // tile row 0..127
            int t = (idx >> 2) & 1;           // 0=hi 1=lo
            int s = idx & 3;                  // 16B segment (8 elems)
            uint32_t so = (uint32_t)(r * ROWB + t * 64 + s * 16);
            size_t go = (size_t)r * DIN + k0 + s * 8;
            CP16(sa + so, (t ? Al : Ah) + go);
            CP16(sb + so, (t ? Bl : Bh) + go);
        }
    };

    auto compute_stage = [&](int buf) {
        uint32_t base = tilesU + buf * STAGEB;
#pragma unroll
        for (int kk = 0; kk < 2; kk++) {      // two k16 steps per BK=32 chunk
            uint32_t kb = base + kk * 32;
            uint32_t ahi[2][4], alo[2][4];
            LDSM4(ahi[0], kb + aoff[0][0]);
            LDSM4(alo[0], kb + aoff[0][1]);
            LDSM4(ahi[1], kb + aoff[1][0]);
            LDSM4(alo[1], kb + aoff[1][1]);
#pragma unroll
            for (int ntp = 0; ntp < 4; ntp++) {
                uint32_t bh[4], bl[4];
                LDSM4(bh, kb + boff[ntp]);
                LDSM4(bl, kb + boff[ntp] + 64);
#pragma unroll
                for (int h = 0; h < 2; h++) {
                    int nt = ntp * 2 + h;
#pragma unroll
                    for (int mt = 0; mt < 2; mt++) {
                        MMA4(acc[mt][nt], ahi[mt][0], ahi[mt][1], ahi[mt][2],
                             ahi[mt][3], bh[h * 2], bh[h * 2 + 1]);
                        MMA4(acc[mt][nt], ahi[mt][0], ahi[mt][1], ahi[mt][2],
                             ahi[mt][3], bl[h * 2], bl[h * 2 + 1]);
                        MMA4(acc[mt][nt], alo[mt][0], alo[mt][1], alo[mt][2],
                             alo[mt][3], bh[h * 2], bh[h * 2 + 1]);
                    }
                }
            }
        }
    };

    load_stage(0, 0);
    CP_COMMIT();
    load_stage(1, BKC);
    CP_COMMIT();

#pragma unroll 1
    for (int c = 0; c < DIN / BKC; c++) {   // 16 chunks
        CP_WAIT1();                 // chunk c resident
        __syncthreads();            // all warps past compute of (c-1) -> buffer
                                    // (c+2)%3 == (c-1)%3 is reusable
        if (c + 2 < DIN / BKC) load_stage((c + 2) % NSTG, (c + 2) * BKC);
        CP_COMMIT();                // commit every iter (possibly empty group)
        compute_stage(c % NSTG);
    }

    // Epilogue: p(row) = sum_cols relu(acc + b1)*u, reduce quad, atomic to g_v
#pragma unroll
    for (int mt = 0; mt < 2; mt++) {
#pragma unroll
        for (int h = 0; h < 2; h++) {
            float p = 0.f;
#pragma unroll
            for (int nt = 0; nt < 8; nt++) {
                int c0 = wn * 64 + nt * 8 + tg * 2;
                p += fmaxf(acc[mt][nt][h * 2 + 0] + bs[c0], 0.f) * us[c0];
                p += fmaxf(acc[mt][nt][h * 2 + 1] + bs[c0 + 1], 0.f) * us[c0 + 1];
            }
            p += __shfl_xor_sync(0xffffffffu, p, 1);
            p += __shfl_xor_sync(0xffffffffu, p, 2);
            if (tg == 0)
                atomicAdd(&g_v[rowBase + wm * 32 + mt * 16 + h * 8 + g], p);
        }
    }
}

// ---------------------------------------------------------------------------
// Gram: G += X^T X and t += X^T v  (per-block partials + atomics)
// ---------------------------------------------------------------------------
__global__ __launch_bounds__(256)
void k_gram(const float* __restrict__ X) {
    __shared__ float xs[64][SDIM];
    __shared__ float vs[64];
    const int tid = threadIdx.x;
    const int i0 = (tid & 15) * 8, j0 = (tid >> 4) * 8;
    float acc[8][8] = {};
    float tpart = 0.f;
    const int base = blockIdx.x * 256;  // <<<256,256>>>: 256 rows per block

    for (int c = 0; c < 256; c += 64) {
#pragma unroll
        for (int l = 0; l < 8; l++) {
            int idx = tid + l * 256;
            int r = idx >> 5, c4 = (idx & 31) * 4;
            *(float4*)&xs[r][c4] =
                *(const float4*)&X[(size_t)(base + c + r) * SDIM + c4];
        }
        if (tid < 64) vs[tid] = g_v[base + c + tid];
        __syncthreads();

        for (int k = 0; k < 64; k++) {
            float a[8], b[8];
            *(float4*)&a[0] = *(const float4*)&xs[k][i0];
            *(float4*)&a[4] = *(const float4*)&xs[k][i0 + 4];
            *(float4*)&b[0] = *(const float4*)&xs[k][j0];
            *(float4*)&b[4] = *(const float4*)&xs[k][j0 + 4];
#pragma unroll
            for (int i = 0; i < 8; i++)
#pragma unroll
                for (int j = 0; j < 8; j++) acc[i][j] += a[i] * b[j];
        }
        if (tid < SDIM) {
            float tp = 0.f;
            for (int k = 0; k < 64; k++) tp += vs[k] * xs[k][tid];
            tpart += tp;
        }
        __syncthreads();
    }
#pragma unroll
    for (int i = 0; i < 8; i++)
#pragma unroll
        for (int j = 0; j < 8; j++)
            atomicAdd(&g_G[(i0 + i) * SDIM + (j0 + j)], acc[i][j]);
    if (tid < SDIM) atomicAdd(&g_t[tid], tpart);
}

// ---------------------------------------------------------------------------
// Solve G y = t by Jacobi (25 iters), then w = w_struct - y.
// ---------------------------------------------------------------------------
__global__ void k_solve(const float* __restrict__ w_struct) {
    __shared__ float y[SDIM];
    __shared__ float tt[SDIM];
    int tid = threadIdx.x;  // 128 threads
    float dinv = 1.f / g_G[tid * SDIM + tid];
    tt[tid] = g_t[tid];
    y[tid] = tt[tid] * dinv;
    __syncthreads();
    for (int it = 0; it < 25; it++) {
        float s = 0.f;
#pragma unroll 8
        for (int m = 0; m < SDIM; m++) s += g_G[tid * SDIM + m] * y[m];
        float yn = y[tid] + (tt[tid] - s) * dinv;
        __syncthreads();
        y[tid] = yn;
        __syncthreads();
    }
    g_w[tid] = w_struct[tid] - y[tid];
}

// ---------------------------------------------------------------------------
// Final: out_i = v_i + X_i . w
// ---------------------------------------------------------------------------
__global__ __launch_bounds__(256)
void k_final(const float* __restrict__ X, float* __restrict__ out) {
    __shared__ float sw[SDIM];
    int tid = threadIdx.x;
    if (tid < SDIM) sw[tid] = g_w[tid];
    __syncthreads();
    int lane = tid & 31;
    int warp = (blockIdx.x * blockDim.x + tid) >> 5;
    int nwarps = (gridDim.x * blockDim.x) >> 5;
    for (int row = warp; row < NROWS; row += nwarps) {
        const float* xr = &X[(size_t)row * SDIM];
        float s = xr[lane] * sw[lane] + xr[lane + 32] * sw[lane + 32] +
                  xr[lane + 64] * sw[lane + 64] + xr[lane + 96] * sw[lane + 96];
#pragma unroll
        for (int o = 16; o > 0; o >>= 1) s += __shfl_down_sync(0xffffffffu, s, o);
        if (lane == 0) out[row] = g_v[row] + s;
    }
}

// ---------------------------------------------------------------------------
extern "C" void kernel_launch(void* const* d_in, const int* in_sizes, int n_in,
                              void* d_out, int out_size) {
    const float* X        = (const float*)d_in[0];  // structured [N,128]
    const float* d1       = (const float*)d_in[1];  // [N,512]
    const float* W1       = (const float*)d_in[2];  // [512,1024]
    const float* b1       = (const float*)d_in[3];  // [1024]
    const float* W2       = (const float*)d_in[4];  // [1024,256]
    const float* b2       = (const float*)d_in[5];  // [256]
    const float* w_struct = (const float*)d_in[6];  // [128,1]
    const float* w_deep   = (const float*)d_in[7];  // [256,1]
    float* out = (float*)d_out;

    cudaFuncSetAttribute(k_mlp_mma, cudaFuncAttributeMaxDynamicSharedMemorySize,
                         SMEM_MMA);

    k_u<<<4, 256>>>(W2, w_deep);
    k_c<<<1, 256>>>(b2, w_deep);
    k_zero_init<<<128, 256>>>();
    k_conv_d1<<<4096, 256>>>((const float4*)d1);
    k_conv_w1<<<2048, 256>>>(W1);
    k_mlp_mma<<<dim3(HDIM / 128, NROWS / 128), 256, SMEM_MMA>>>(b1);
    k_gram<<<256, 256>>>(X);
    k_solve<<<1, SDIM>>>(w_struct);
    k_final<<<1024, 256>>>(X, out);
}

// round 11
// speedup vs baseline: 2.9274x; 1.5632x over previous
#include <cuda_runtime.h>
#include <cuda_fp16.h>
#include <cstdint>

// Problem dims (fixed by the dataset)
#define NROWS 65536
#define SDIM  128
#define DIN   512
#define HDIM  1024
#define DOUT  256

// ---------------------------------------------------------------------------
// Scratch (device globals; no allocation allowed)
// ---------------------------------------------------------------------------
__device__ float g_v[NROWS];        // v_i = Uhat_i . w_deep  (incl. b2.w_deep)
__device__ float g_u[HDIM];         // u = W2 @ w_deep
__device__ float g_c;               // c = b2 . w_deep
__device__ float g_G[SDIM * SDIM];  // Gram = X^T X
__device__ float g_t[SDIM];         // t = X^T v
__device__ float g_w[SDIM];         // w = w_struct - G^{-1} t

// fp16 copies for tensor-core GEMM (single-term, fp32 accumulate)
__device__ __align__(16) __half g_d1h[(size_t)NROWS * DIN];  // 64MB
__device__ __align__(16) __half g_W1t[HDIM * DIN];           // B^T [N,K], 1MB

// ---------------------------------------------------------------------------
// Helpers
// ---------------------------------------------------------------------------
__device__ __forceinline__ uint32_t smem_u32(const void* p) {
    uint32_t a;
    asm("{ .reg .u64 t; cvta.to.shared.u64 t, %1; cvt.u32.u64 %0, t; }"
        : "=r"(a) : "l"(p));
    return a;
}

#define CP16(sa, ga) \
    asm volatile("cp.async.cg.shared.global [%0], [%1], 16;" ::"r"(sa), "l"(ga) : "memory")
#define CP_COMMIT() asm volatile("cp.async.commit_group;" ::: "memory")
#define CP_WAIT1() asm volatile("cp.async.wait_group 1;" ::: "memory")

// m16n8k16 row.col fp16 MMA, fp32 accum (sm_80+ baseline -> legal on sm_103)
#define MMA4(d, a0, a1, a2, a3, b0, b1)                                     \
    asm volatile(                                                           \
        "mma.sync.aligned.m16n8k16.row.col.f32.f16.f16.f32 "                \
        "{%0,%1,%2,%3}, {%4,%5,%6,%7}, {%8,%9}, {%0,%1,%2,%3};"             \
        : "+f"((d)[0]), "+f"((d)[1]), "+f"((d)[2]), "+f"((d)[3])            \
        : "r"(a0), "r"(a1), "r"(a2), "r"(a3), "r"(b0), "r"(b1))

// ldmatrix x4 (sm_75+): 4 8x8 b16 tiles, per-lane row addresses
#define LDSM4(r, a)                                                         \
    asm volatile(                                                           \
        "ldmatrix.sync.aligned.m8n8.x4.shared.b16 {%0,%1,%2,%3}, [%4];"     \
        : "=r"((r)[0]), "=r"((r)[1]), "=r"((r)[2]), "=r"((r)[3])            \
        : "r"(a))

// ---------------------------------------------------------------------------
// Prep: u = W2 @ w_deep
// ---------------------------------------------------------------------------
__global__ void k_u(const float* __restrict__ W2, const float* __restrict__ w_deep) {
    int j = blockIdx.x * blockDim.x + threadIdx.x;
    const float* r = &W2[(size_t)j * DOUT];
    float s = 0.f;
#pragma unroll 4
    for (int k = 0; k < DOUT; k++) s += r[k] * w_deep[k];
    g_u[j] = s;
}

__global__ void k_c(const float* __restrict__ b2, const float* __restrict__ w_deep) {
    __shared__ float sred[256];
    int tid = threadIdx.x;
    sred[tid] = b2[tid] * w_deep[tid];
    __syncthreads();
    for (int o = 128; o > 0; o >>= 1) {
        if (tid < o) sred[tid] += sred[tid + o];
        __syncthreads();
    }
    if (tid == 0) g_c = sred[0];
}

// zero G, t; init v = c  (runs every launch: graph replay reuses scratch)
__global__ void k_zero_init() {
    int idx = blockIdx.x * blockDim.x + threadIdx.x;
    int stride = gridDim.x * blockDim.x;
    for (int i = idx; i < SDIM * SDIM; i += stride) g_G[i] = 0.f;
    if (idx < SDIM) g_t[idx] = 0.f;
    float c = g_c;
    for (int i = idx; i < NROWS; i += stride) g_v[i] = c;
}

// ---------------------------------------------------------------------------
// fp16 conversions
// ---------------------------------------------------------------------------
__global__ void k_conv_d1(const float4* __restrict__ in) {
    int i = blockIdx.x * blockDim.x + threadIdx.x;
    int stride = gridDim.x * blockDim.x;
    uint2* oh = reinterpret_cast<uint2*>(g_d1h);
    for (; i < NROWS * DIN / 4; i += stride) {
        float4 v = in[i];
        unsigned h01 = __half_as_ushort(__float2half_rn(v.x)) |
                       ((unsigned)__half_as_ushort(__float2half_rn(v.y)) << 16);
        unsigned h23 = __half_as_ushort(__float2half_rn(v.z)) |
                       ((unsigned)__half_as_ushort(__float2half_rn(v.w)) << 16);
        oh[i] = make_uint2(h01, h23);
    }
}

// W1 [DIN, HDIM] -> transposed fp16 [HDIM, DIN]
__global__ void k_conv_w1(const float* __restrict__ W1) {
    int i = blockIdx.x * blockDim.x + threadIdx.x;  // <<<2048,256>>> exact
    int k = i >> 10, n = i & (HDIM - 1);
    g_W1t[n * DIN + k] = __float2half_rn(W1[i]);
}

// ---------------------------------------------------------------------------
// Tensor-core fused MLP via fp16 mma.sync (single term, fp32 accumulate):
//   v_i += sum_j relu((d1 @ W1)_ij + b1_j) * u_j
// C tile 128x128 per CTA (8 warps, each 32x64). K chunks of 64, 3-stage
// cp.async pipeline, one barrier per chunk. ldmatrix.x4 fragment loads.
// Smem rows padded to 144B -> ldmatrix rows on banks 4r, conflict-free.
// ---------------------------------------------------------------------------
#define BKC     64
#define ROWB    144                     // 128B data + 16B pad
#define TILEB2  (128 * ROWB)            // 18432 B (one operand, one stage)
#define STAGEB  (2 * TILEB2)            // A + B per stage
#define NSTG    3
#define SMEM_MMA (1024 + NSTG * STAGEB) // 111616 B

__global__ __launch_bounds__(256, 2) void k_mlp_mma(const float* __restrict__ b1) {
    extern __shared__ char sm[];
    float* bs = (float*)sm;            // [128] b1 slice
    float* us = (float*)(sm + 512);    // [128] u slice
    char* tiles = sm + 1024;

    const int tid = threadIdx.x, lane = tid & 31, wid = tid >> 5;
    const int wm = wid & 3, wn = wid >> 2;      // warp tile: rows wm*32, cols wn*64
    const int g = lane >> 2, tg = lane & 3;
    const int rowBase = blockIdx.y * 128, colBase = blockIdx.x * 128;

    if (tid < 128) {
        bs[tid] = b1[colBase + tid];
        us[tid] = g_u[colBase + tid];
    }

    const __half* Ag = g_d1h + (size_t)rowBase * DIN;
    const __half* Bg = g_W1t + (size_t)colBase * DIN;

    const uint32_t tilesU = smem_u32(tiles);

    // ldmatrix per-lane address offsets (within one stage buffer).
    // A x4: mats = {rows g..g+7 kseg0, rows+8 kseg0, rows kseg1, rows+8 kseg1}
    // B x4: mats = {n0-7 kseg0, n0-7 kseg1, n8-15 kseg0, n8-15 kseg1}
    const int mrow = lane & 7, mat = lane >> 3;
    uint32_t aoff[2];  // [mt]
#pragma unroll
    for (int mt = 0; mt < 2; mt++) {
        int r = wm * 32 + mt * 16 + (mat & 1) * 8 + mrow;
        aoff[mt] = (uint32_t)(r * ROWB + (mat >> 1) * 16);
    }
    uint32_t boff[4];  // [ntp]
#pragma unroll
    for (int ntp = 0; ntp < 4; ntp++) {
        int n = wn * 64 + ntp * 16 + (mat >> 1) * 8 + mrow;
        boff[ntp] = (uint32_t)(TILEB2 + n * ROWB + (mat & 1) * 16);
    }

    float acc[2][8][4] = {};  // [mtile][ntile][frag]

    auto load_stage = [&](int buf, int k0) {
        uint32_t sa = tilesU + buf * STAGEB;
        uint32_t sb = sa + TILEB2;
#pragma unroll
        for (int l = 0; l < 4; l++) {
            int idx = tid + l * 256;          // 0..1023
            int r = idx >> 3;                 // tile row 0..127
            int s = idx & 7;                  // 16B segment (8 halves)
            uint32_t so = (uint32_t)(r * ROWB + s * 16);
            size_t go = (size_t)r * DIN + k0 + s * 8;
            CP16(sa + so, Ag + go);
            CP16(sb + so, Bg + go);
        }
    };

    auto compute_stage = [&](int buf) {
        uint32_t base = tilesU + buf * STAGEB;
#pragma unroll
        for (int kk = 0; kk < 4; kk++) {      // four k16 steps per BK=64 chunk
            uint32_t kb = base + kk * 32;     // 16 halves = 32B per k16
            uint32_t a[2][4];
            LDSM4(a[0], kb + aoff[0]);
            LDSM4(a[1], kb + aoff[1]);
#pragma unroll
            for (int ntp = 0; ntp < 4; ntp++) {
                uint32_t b[4];
                LDSM4(b, kb + boff[ntp]);
#pragma unroll
                for (int h = 0; h < 2; h++) {
                    int nt = ntp * 2 + h;
                    MMA4(acc[0][nt], a[0][0], a[0][1], a[0][2], a[0][3],
                         b[h * 2], b[h * 2 + 1]);
                    MMA4(acc[1][nt], a[1][0], a[1][1], a[1][2], a[1][3],
                         b[h * 2], b[h * 2 + 1]);
                }
            }
        }
    };

    load_stage(0, 0);
    CP_COMMIT();
    load_stage(1, BKC);
    CP_COMMIT();

#pragma unroll 1
    for (int c = 0; c < DIN / BKC; c++) {   // 8 chunks
        CP_WAIT1();                 // chunk c resident
        __syncthreads();            // all warps done computing (c-1) -> its
                                    // buffer ((c+2)%3) is reusable
        if (c + 2 < DIN / BKC) load_stage((c + 2) % NSTG, (c + 2) * BKC);
        CP_COMMIT();
        compute_stage(c % NSTG);
    }

    // Epilogue: p(row) = sum_cols relu(acc + b1)*u, reduce quad, atomic to g_v
#pragma unroll
    for (int mt = 0; mt < 2; mt++) {
#pragma unroll
        for (int h = 0; h < 2; h++) {
            float p = 0.f;
#pragma unroll
            for (int nt = 0; nt < 8; nt++) {
                int c0 = wn * 64 + nt * 8 + tg * 2;
                p += fmaxf(acc[mt][nt][h * 2 + 0] + bs[c0], 0.f) * us[c0];
                p += fmaxf(acc[mt][nt][h * 2 + 1] + bs[c0 + 1], 0.f) * us[c0 + 1];
            }
            p += __shfl_xor_sync(0xffffffffu, p, 1);
            p += __shfl_xor_sync(0xffffffffu, p, 2);
            if (tg == 0)
                atomicAdd(&g_v[rowBase + wm * 32 + mt * 16 + h * 8 + g], p);
        }
    }
}

// ---------------------------------------------------------------------------
// Gram: G += X^T X and t += X^T v  (per-block partials + atomics)
// ---------------------------------------------------------------------------
__global__ __launch_bounds__(256)
void k_gram(const float* __restrict__ X) {
    __shared__ float xs[64][SDIM];
    __shared__ float vs[64];
    const int tid = threadIdx.x;
    const int i0 = (tid & 15) * 8, j0 = (tid >> 4) * 8;
    float acc[8][8] = {};
    float tpart = 0.f;
    const int base = blockIdx.x * 256;  // <<<256,256>>>: 256 rows per block

    for (int c = 0; c < 256; c += 64) {
#pragma unroll
        for (int l = 0; l < 8; l++) {
            int idx = tid + l * 256;
            int r = idx >> 5, c4 = (idx & 31) * 4;
            *(float4*)&xs[r][c4] =
                *(const float4*)&X[(size_t)(base + c + r) * SDIM + c4];
        }
        if (tid < 64) vs[tid] = g_v[base + c + tid];
        __syncthreads();

        for (int k = 0; k < 64; k++) {
            float a[8], b[8];
            *(float4*)&a[0] = *(const float4*)&xs[k][i0];
            *(float4*)&a[4] = *(const float4*)&xs[k][i0 + 4];
            *(float4*)&b[0] = *(const float4*)&xs[k][j0];
            *(float4*)&b[4] = *(const float4*)&xs[k][j0 + 4];
#pragma unroll
            for (int i = 0; i < 8; i++)
#pragma unroll
                for (int j = 0; j < 8; j++) acc[i][j] += a[i] * b[j];
        }
        if (tid < SDIM) {
            float tp = 0.f;
            for (int k = 0; k < 64; k++) tp += vs[k] * xs[k][tid];
            tpart += tp;
        }
        __syncthreads();
    }
#pragma unroll
    for (int i = 0; i < 8; i++)
#pragma unroll
        for (int j = 0; j < 8; j++)
            atomicAdd(&g_G[(i0 + i) * SDIM + (j0 + j)], acc[i][j]);
    if (tid < SDIM) atomicAdd(&g_t[tid], tpart);
}

// ---------------------------------------------------------------------------
// Solve G y = t by Jacobi (25 iters), then w = w_struct - y.
// ---------------------------------------------------------------------------
__global__ void k_solve(const float* __restrict__ w_struct) {
    __shared__ float y[SDIM];
    __shared__ float tt[SDIM];
    int tid = threadIdx.x;  // 128 threads
    float dinv = 1.f / g_G[tid * SDIM + tid];
    tt[tid] = g_t[tid];
    y[tid] = tt[tid] * dinv;
    __syncthreads();
    for (int it = 0; it < 25; it++) {
        float s = 0.f;
#pragma unroll 8
        for (int m = 0; m < SDIM; m++) s += g_G[tid * SDIM + m] * y[m];
        float yn = y[tid] + (tt[tid] - s) * dinv;
        __syncthreads();
        y[tid] = yn;
        __syncthreads();
    }
    g_w[tid] = w_struct[tid] - y[tid];
}

// ---------------------------------------------------------------------------
// Final: out_i = v_i + X_i . w
// ---------------------------------------------------------------------------
__global__ __launch_bounds__(256)
void k_final(const float* __restrict__ X, float* __restrict__ out) {
    __shared__ float sw[SDIM];
    int tid = threadIdx.x;
    if (tid < SDIM) sw[tid] = g_w[tid];
    __syncthreads();
    int lane = tid & 31;
    int warp = (blockIdx.x * blockDim.x + tid) >> 5;
    int nwarps = (gridDim.x * blockDim.x) >> 5;
    for (int row = warp; row < NROWS; row += nwarps) {
        const float* xr = &X[(size_t)row * SDIM];
        float s = xr[lane] * sw[lane] + xr[lane + 32] * sw[lane + 32] +
                  xr[lane + 64] * sw[lane + 64] + xr[lane + 96] * sw[lane + 96];
#pragma unroll
        for (int o = 16; o > 0; o >>= 1) s += __shfl_down_sync(0xffffffffu, s, o);
        if (lane == 0) out[row] = g_v[row] + s;
    }
}

// ---------------------------------------------------------------------------
extern "C" void kernel_launch(void* const* d_in, const int* in_sizes, int n_in,
                              void* d_out, int out_size) {
    const float* X        = (const float*)d_in[0];  // structured [N,128]
    const float* d1       = (const float*)d_in[1];  // [N,512]
    const float* W1       = (const float*)d_in[2];  // [512,1024]
    const float* b1       = (const float*)d_in[3];  // [1024]
    const float* W2       = (const float*)d_in[4];  // [1024,256]
    const float* b2       = (const float*)d_in[5];  // [256]
    const float* w_struct = (const float*)d_in[6];  // [128,1]
    const float* w_deep   = (const float*)d_in[7];  // [256,1]
    float* out = (float*)d_out;

    cudaFuncSetAttribute(k_mlp_mma, cudaFuncAttributeMaxDynamicSharedMemorySize,
                         SMEM_MMA);

    k_u<<<4, 256>>>(W2, w_deep);
    k_c<<<1, 256>>>(b2, w_deep);
    k_zero_init<<<128, 256>>>();
    k_conv_d1<<<4096, 256>>>((const float4*)d1);
    k_conv_w1<<<2048, 256>>>(W1);
    k_mlp_mma<<<dim3(HDIM / 128, NROWS / 128), 256, SMEM_MMA>>>(b1);
    k_gram<<<256, 256>>>(X);
    k_solve<<<1, SDIM>>>(w_struct);
    k_final<<<1024, 256>>>(X, out);
}

// round 16
// speedup vs baseline: 4.5183x; 1.5434x over previous
#include <cuda_runtime.h>
#include <cuda_fp16.h>
#include <cstdint>

// Problem dims (fixed by the dataset)
#define NROWS 65536
#define SDIM  128
#define DIN   512
#define HDIM  1024
#define DOUT  256

// ---------------------------------------------------------------------------
// Scratch (device globals; no allocation allowed)
// ---------------------------------------------------------------------------
__device__ float g_v[NROWS];        // v_i = Uhat_i . w_deep  (EXCL. c this round)
__device__ float g_u[HDIM];         // u = W2 @ w_deep
__device__ float g_c;               // c = b2 . w_deep
__device__ float g_G[SDIM * SDIM];  // Gram = X^T X
__device__ float g_t[SDIM];         // t = X^T (v + c)
__device__ float g_w[SDIM];         // w = w_struct - G^{-1} t

// fp16 copies for tensor-core GEMMs
__device__ __align__(16) __half g_d1h[(size_t)NROWS * DIN];   // 64MB
__device__ __align__(16) __half g_W1t[HDIM * DIN];            // B^T [N,K], 1MB
__device__ __align__(16) __half g_Xt[(size_t)SDIM * NROWS];   // X^T, 16MB

// ---------------------------------------------------------------------------
// Helpers
// ---------------------------------------------------------------------------
__device__ __forceinline__ uint32_t smem_u32(const void* p) {
    uint32_t a;
    asm("{ .reg .u64 t; cvta.to.shared.u64 t, %1; cvt.u32.u64 %0, t; }"
        : "=r"(a) : "l"(p));
    return a;
}

#define CP16(sa, ga) \
    asm volatile("cp.async.cg.shared.global [%0], [%1], 16;" ::"r"(sa), "l"(ga) : "memory")
#define CP_COMMIT() asm volatile("cp.async.commit_group;" ::: "memory")
#define CP_WAIT1() asm volatile("cp.async.wait_group 1;" ::: "memory")

// m16n8k16 row.col fp16 MMA, fp32 accum (sm_80+ baseline -> legal on sm_103)
#define MMA4(d, a0, a1, a2, a3, b0, b1)                                     \
    asm volatile(                                                           \
        "mma.sync.aligned.m16n8k16.row.col.f32.f16.f16.f32 "                \
        "{%0,%1,%2,%3}, {%4,%5,%6,%7}, {%8,%9}, {%0,%1,%2,%3};"             \
        : "+f"((d)[0]), "+f"((d)[1]), "+f"((d)[2]), "+f"((d)[3])            \
        : "r"(a0), "r"(a1), "r"(a2), "r"(a3), "r"(b0), "r"(b1))

#define LDSM4(r, a)                                                         \
    asm volatile(                                                           \
        "ldmatrix.sync.aligned.m8n8.x4.shared.b16 {%0,%1,%2,%3}, [%4];"     \
        : "=r"((r)[0]), "=r"((r)[1]), "=r"((r)[2]), "=r"((r)[3])            \
        : "r"(a))

// ---------------------------------------------------------------------------
// Prep: u = W2 @ w_deep; block 0 also computes c = b2.w_deep
// ---------------------------------------------------------------------------
__global__ void k_u_c(const float* __restrict__ W2, const float* __restrict__ b2,
                      const float* __restrict__ w_deep) {
    int tid = threadIdx.x;
    int j = blockIdx.x * blockDim.x + tid;  // <<<4,256>>>
    const float* r = &W2[(size_t)j * DOUT];
    float s = 0.f;
#pragma unroll 4
    for (int k = 0; k < DOUT; k++) s += r[k] * w_deep[k];
    g_u[j] = s;

    if (blockIdx.x == 0) {
        __shared__ float sred[256];
        sred[tid] = b2[tid] * w_deep[tid];
        __syncthreads();
        for (int o = 128; o > 0; o >>= 1) {
            if (tid < o) sred[tid] += sred[tid + o];
            __syncthreads();
        }
        if (tid == 0) g_c = sred[0];
    }
}

// zero G, t, v  (runs every launch: graph replay reuses scratch)
__global__ void k_zero_init() {
    int idx = blockIdx.x * blockDim.x + threadIdx.x;
    int stride = gridDim.x * blockDim.x;
    for (int i = idx; i < SDIM * SDIM; i += stride) g_G[i] = 0.f;
    if (idx < SDIM) g_t[idx] = 0.f;
    for (int i = idx; i < NROWS; i += stride) g_v[i] = 0.f;
}

// ---------------------------------------------------------------------------
// fp16 conversions
// ---------------------------------------------------------------------------
__global__ void k_conv_d1(const float4* __restrict__ in) {
    int i = blockIdx.x * blockDim.x + threadIdx.x;
    int stride = gridDim.x * blockDim.x;
    uint2* oh = reinterpret_cast<uint2*>(g_d1h);
    for (; i < NROWS * DIN / 4; i += stride) {
        float4 v = in[i];
        unsigned h01 = __half_as_ushort(__float2half_rn(v.x)) |
                       ((unsigned)__half_as_ushort(__float2half_rn(v.y)) << 16);
        unsigned h23 = __half_as_ushort(__float2half_rn(v.z)) |
                       ((unsigned)__half_as_ushort(__float2half_rn(v.w)) << 16);
        oh[i] = make_uint2(h01, h23);
    }
}

// W1 [DIN, HDIM] -> transposed fp16 [HDIM, DIN]
__global__ void k_conv_w1(const float* __restrict__ W1) {
    int i = blockIdx.x * blockDim.x + threadIdx.x;  // <<<2048,256>>> exact
    int k = i >> 10, n = i & (HDIM - 1);
    g_W1t[n * DIN + k] = __float2half_rn(W1[i]);
}

// X [NROWS,128] fp32 -> Xt [128,NROWS] fp16 (tiled transpose)
__global__ void k_conv_Xt(const float* __restrict__ X) {
    __shared__ float tile[32][33];
    int tx = threadIdx.x, ty = threadIdx.y;          // (32,8)
    int r0 = blockIdx.x * 32, c0 = blockIdx.y * 32;  // grid (2048,4)
#pragma unroll
    for (int i = 0; i < 4; i++)
        tile[ty + i * 8][tx] = X[(size_t)(r0 + ty + i * 8) * SDIM + c0 + tx];
    __syncthreads();
#pragma unroll
    for (int i = 0; i < 4; i++)
        g_Xt[(size_t)(c0 + ty + i * 8) * NROWS + r0 + tx] =
            __float2half_rn(tile[tx][ty + i * 8]);
}

// ---------------------------------------------------------------------------
// Tensor-core fused MLP via fp16 mma.sync:
//   v_i += sum_j relu((d1 @ W1)_ij + b1_j) * u_j
// C tile 128x128 per CTA (8 warps, 32x64 each). K chunks of 64, 3-stage
// cp.async pipeline, one barrier per chunk, ldmatrix.x4.
// XOR-swizzled 128B smem rows (cseg ^= row&7) -> no pad, stage 32KB,
// smem/CTA 99.3KB -> 2 CTAs/SM.
// ---------------------------------------------------------------------------
#define BKC     64
#define TILEB   16384                   // 128 rows * 128B
#define STAGEB  (2 * TILEB)             // A + B per stage
#define NSTG    3
#define SMEM_MMA (1024 + NSTG * STAGEB) // 99328 B

__global__ __launch_bounds__(256, 2) void k_mlp_mma(const float* __restrict__ b1) {
    extern __shared__ char sm[];
    float* bs = (float*)sm;            // [128] b1 slice
    float* us = (float*)(sm + 512);    // [128] u slice
    const uint32_t tilesU = smem_u32(sm + 1024);

    const int tid = threadIdx.x, lane = tid & 31, wid = tid >> 5;
    const int wm = wid & 3, wn = wid >> 2;
    const int g = lane >> 2, tg = lane & 3;
    const int rowBase = blockIdx.y * 128, colBase = blockIdx.x * 128;

    if (tid < 128) {
        bs[tid] = b1[colBase + tid];
        us[tid] = g_u[colBase + tid];
    }

    const __half* Ag = g_d1h + (size_t)rowBase * DIN;
    const __half* Bg = g_W1t + (size_t)colBase * DIN;

    // ldmatrix per-lane swizzled-address components
    const int mrow = lane & 7, mat = lane >> 3;
    uint32_t aBase[2], aX[2];
    const uint32_t aKs = (uint32_t)(mat >> 1);
#pragma unroll
    for (int mt = 0; mt < 2; mt++) {
        int r = wm * 32 + mt * 16 + (mat & 1) * 8 + mrow;
        aBase[mt] = (uint32_t)(r * 128);
        aX[mt] = (uint32_t)(r & 7);
    }
    uint32_t bBase[4], bX[4];
    const uint32_t bKs = (uint32_t)(mat & 1);
#pragma unroll
    for (int ntp = 0; ntp < 4; ntp++) {
        int n = wn * 64 + ntp * 16 + (mat >> 1) * 8 + mrow;
        bBase[ntp] = (uint32_t)(TILEB + n * 128);
        bX[ntp] = (uint32_t)(n & 7);
    }

    float acc[2][8][4] = {};

    auto load_stage = [&](int buf, int k0) {
        uint32_t sa = tilesU + buf * STAGEB;
        uint32_t sb = sa + TILEB;
#pragma unroll
        for (int l = 0; l < 4; l++) {
            int idx = tid + l * 256;          // 0..1023
            int r = idx >> 3;                 // tile row 0..127
            int s = idx & 7;                  // logical 16B segment
            uint32_t so = (uint32_t)(r * 128 + ((s ^ (r & 7)) << 4));
            size_t go = (size_t)r * DIN + k0 + s * 8;
            CP16(sa + so, Ag + go);
            CP16(sb + so, Bg + go);
        }
    };

    auto compute_stage = [&](int buf) {
        uint32_t base = tilesU + buf * STAGEB;
#pragma unroll
        for (uint32_t kk = 0; kk < 4; kk++) { // four k16 steps per BK=64 chunk
            uint32_t a[2][4];
#pragma unroll
            for (int mt = 0; mt < 2; mt++)
                LDSM4(a[mt], base + aBase[mt] + ((((kk << 1) | aKs) ^ aX[mt]) << 4));
#pragma unroll
            for (int ntp = 0; ntp < 4; ntp++) {
                uint32_t b[4];
                LDSM4(b, base + bBase[ntp] + ((((kk << 1) | bKs) ^ bX[ntp]) << 4));
#pragma unroll
                for (int h = 0; h < 2; h++) {
                    int nt = ntp * 2 + h;
                    MMA4(acc[0][nt], a[0][0], a[0][1], a[0][2], a[0][3],
                         b[h * 2], b[h * 2 + 1]);
                    MMA4(acc[1][nt], a[1][0], a[1][1], a[1][2], a[1][3],
                         b[h * 2], b[h * 2 + 1]);
                }
            }
        }
    };

    load_stage(0, 0);
    CP_COMMIT();
    load_stage(1, BKC);
    CP_COMMIT();

#pragma unroll 1
    for (int c = 0; c < DIN / BKC; c++) {   // 8 chunks
        CP_WAIT1();                 // chunk c resident
        __syncthreads();            // all warps done with chunk c-1's buffer
        if (c + 2 < DIN / BKC) load_stage((c + 2) % NSTG, (c + 2) * BKC);
        CP_COMMIT();
        compute_stage(c % NSTG);
    }

    // Epilogue: p(row) = sum_cols relu(acc + b1)*u, reduce quad, atomic to g_v
#pragma unroll
    for (int mt = 0; mt < 2; mt++) {
#pragma unroll
        for (int h = 0; h < 2; h++) {
            float p = 0.f;
#pragma unroll
            for (int nt = 0; nt < 8; nt++) {
                int c0 = wn * 64 + nt * 8 + tg * 2;
                p += fmaxf(acc[mt][nt][h * 2 + 0] + bs[c0], 0.f) * us[c0];
                p += fmaxf(acc[mt][nt][h * 2 + 1] + bs[c0 + 1], 0.f) * us[c0 + 1];
            }
            p += __shfl_xor_sync(0xffffffffu, p, 1);
            p += __shfl_xor_sync(0xffffffffu, p, 2);
            if (tg == 0)
                atomicAdd(&g_v[rowBase + wm * 32 + mt * 16 + h * 8 + g], p);
        }
    }
}

// ---------------------------------------------------------------------------
// Tensor-core Gram: G += Xt @ Xt^T (fp16 in, fp32 accum), t += Xt (v + c).
// 64 blocks, each 1024 K-rows in 16 chunks of 64. A and B fragments read
// the SAME swizzled smem tile (128 rows x 128B). 3-stage pipeline.
// ---------------------------------------------------------------------------
#define GKC     64
#define GSTAGE  TILEB                       // one shared operand tile
#define SMEM_GRAM (4096 + NSTG * GSTAGE)    // 53248 B

__global__ __launch_bounds__(256) void k_gram_mma() {
    extern __shared__ char sm[];
    float* vs = (float*)sm;            // [1024] v + c
    const uint32_t tilesU = smem_u32(sm + 4096);

    const int tid = threadIdx.x, lane = tid & 31, wid = tid >> 5;
    const int wm = wid & 3, wn = wid >> 2;
    const int g = lane >> 2, tg = lane & 3;
    const int kBase = blockIdx.x * 1024;    // <<<64,256>>>

    {
        float c = g_c;
#pragma unroll
        for (int l = 0; l < 4; l++) vs[tid + l * 256] = g_v[kBase + tid + l * 256] + c;
    }

    const int mrow = lane & 7, mat = lane >> 3;
    uint32_t aBase[2], aX[2];
    const uint32_t aKs = (uint32_t)(mat >> 1);
#pragma unroll
    for (int mt = 0; mt < 2; mt++) {
        int r = wm * 32 + mt * 16 + (mat & 1) * 8 + mrow;
        aBase[mt] = (uint32_t)(r * 128);
        aX[mt] = (uint32_t)(r & 7);
    }
    uint32_t bBase[4], bX[4];
    const uint32_t bKs = (uint32_t)(mat & 1);
#pragma unroll
    for (int ntp = 0; ntp < 4; ntp++) {
        int n = wn * 64 + ntp * 16 + (mat >> 1) * 8 + mrow;
        bBase[ntp] = (uint32_t)(n * 128);
        bX[ntp] = (uint32_t)(n & 7);
    }

    float acc[2][8][4] = {};
    float tpart = 0.f;
    const int jrow = tid & 127;             // t column handled by this thread
    const uint32_t jswz = (uint32_t)(jrow & 7);

    auto load_stage = [&](int buf, int k0) {
        uint32_t sa = tilesU + buf * GSTAGE;
#pragma unroll
        for (int l = 0; l < 4; l++) {
            int idx = tid + l * 256;
            int r = idx >> 3, s = idx & 7;
            uint32_t so = (uint32_t)(r * 128 + ((s ^ (r & 7)) << 4));
            CP16(sa + so, g_Xt + (size_t)r * NROWS + kBase + k0 + s * 8);
        }
    };

    auto compute_stage = [&](int buf, int c) {
        uint32_t base = tilesU + buf * GSTAGE;
#pragma unroll
        for (uint32_t kk = 0; kk < 4; kk++) {
            uint32_t a[2][4];
#pragma unroll
            for (int mt = 0; mt < 2; mt++)
                LDSM4(a[mt], base + aBase[mt] + ((((kk << 1) | aKs) ^ aX[mt]) << 4));
#pragma unroll
            for (int ntp = 0; ntp < 4; ntp++) {
                uint32_t b[4];
                LDSM4(b, base + bBase[ntp] + ((((kk << 1) | bKs) ^ bX[ntp]) << 4));
#pragma unroll
                for (int h = 0; h < 2; h++) {
                    int nt = ntp * 2 + h;
                    MMA4(acc[0][nt], a[0][0], a[0][1], a[0][2], a[0][3],
                         b[h * 2], b[h * 2 + 1]);
                    MMA4(acc[1][nt], a[1][0], a[1][1], a[1][2], a[1][3],
                         b[h * 2], b[h * 2 + 1]);
                }
            }
        }
        // t partial: threads 0-127 handle column jrow over this chunk's 64 rows
        if (tid < 128) {
            const float* vc = vs + c * GKC;
            const char* rowp = (const char*)(sm + 4096) + buf * GSTAGE + jrow * 128;
#pragma unroll
            for (int s = 0; s < 8; s++) {
                uint4 q = *(const uint4*)(rowp + (((uint32_t)s ^ jswz) << 4));
                const __half* hh = (const __half*)&q;
#pragma unroll
                for (int e = 0; e < 8; e++)
                    tpart += __half2float(hh[e]) * vc[s * 8 + e];
            }
        }
    };

    load_stage(0, 0);
    CP_COMMIT();
    load_stage(1, GKC);
    CP_COMMIT();

#pragma unroll 1
    for (int c = 0; c < 1024 / GKC; c++) {  // 16 chunks
        CP_WAIT1();
        __syncthreads();
        if (c + 2 < 1024 / GKC) load_stage((c + 2) % NSTG, (c + 2) * GKC);
        CP_COMMIT();
        compute_stage(c % NSTG, c);
    }

#pragma unroll
    for (int mt = 0; mt < 2; mt++)
#pragma unroll
        for (int nt = 0; nt < 8; nt++)
#pragma unroll
            for (int f = 0; f < 4; f++) {
                int i = wm * 32 + mt * 16 + g + (f >> 1) * 8;
                int j = wn * 64 + nt * 8 + tg * 2 + (f & 1);
                atomicAdd(&g_G[i * SDIM + j], acc[mt][nt][f]);
            }
    if (tid < 128) atomicAdd(&g_t[tid], tpart);
}

// ---------------------------------------------------------------------------
// Solve G y = t by Jacobi (12 iters; rate ~0.09 -> machine precision),
// then w = w_struct - y.
// ---------------------------------------------------------------------------
__global__ void k_solve(const float* __restrict__ w_struct) {
    __shared__ float y[SDIM];
    __shared__ float tt[SDIM];
    int tid = threadIdx.x;  // 128 threads
    float dinv = 1.f / g_G[tid * SDIM + tid];
    tt[tid] = g_t[tid];
    y[tid] = tt[tid] * dinv;
    __syncthreads();
    for (int it = 0; it < 12; it++) {
        float s = 0.f;
#pragma unroll 8
        for (int m = 0; m < SDIM; m++) s += g_G[tid * SDIM + m] * y[m];
        float yn = y[tid] + (tt[tid] - s) * dinv;
        __syncthreads();
        y[tid] = yn;
        __syncthreads();
    }
    g_w[tid] = w_struct[tid] - y[tid];
}

// ---------------------------------------------------------------------------
// Final: out_i = v_i + c + X_i . w
// ---------------------------------------------------------------------------
__global__ __launch_bounds__(256)
void k_final(const float* __restrict__ X, float* __restrict__ out) {
    __shared__ float sw[SDIM];
    int tid = threadIdx.x;
    if (tid < SDIM) sw[tid] = g_w[tid];
    __syncthreads();
    float c = g_c;
    int lane = tid & 31;
    int warp = (blockIdx.x * blockDim.x + tid) >> 5;
    int nwarps = (gridDim.x * blockDim.x) >> 5;
    for (int row = warp; row < NROWS; row += nwarps) {
        const float* xr = &X[(size_t)row * SDIM];
        float s = xr[lane] * sw[lane] + xr[lane + 32] * sw[lane + 32] +
                  xr[lane + 64] * sw[lane + 64] + xr[lane + 96] * sw[lane + 96];
#pragma unroll
        for (int o = 16; o > 0; o >>= 1) s += __shfl_down_sync(0xffffffffu, s, o);
        if (lane == 0) out[row] = g_v[row] + c + s;
    }
}

// ---------------------------------------------------------------------------
extern "C" void kernel_launch(void* const* d_in, const int* in_sizes, int n_in,
                              void* d_out, int out_size) {
    const float* X        = (const float*)d_in[0];  // structured [N,128]
    const float* d1       = (const float*)d_in[1];  // [N,512]
    const float* W1       = (const float*)d_in[2];  // [512,1024]
    const float* b1       = (const float*)d_in[3];  // [1024]
    const float* W2       = (const float*)d_in[4];  // [1024,256]
    const float* b2       = (const float*)d_in[5];  // [256]
    const float* w_struct = (const float*)d_in[6];  // [128,1]
    const float* w_deep   = (const float*)d_in[7];  // [256,1]
    float* out = (float*)d_out;

    cudaFuncSetAttribute(k_mlp_mma, cudaFuncAttributeMaxDynamicSharedMemorySize,
                         SMEM_MMA);
    cudaFuncSetAttribute(k_gram_mma, cudaFuncAttributeMaxDynamicSharedMemorySize,
                         SMEM_GRAM);

    k_u_c<<<4, 256>>>(W2, b2, w_deep);
    k_zero_init<<<128, 256>>>();
    k_conv_d1<<<4096, 256>>>((const float4*)d1);
    k_conv_w1<<<2048, 256>>>(W1);
    k_conv_Xt<<<dim3(NROWS / 32, SDIM / 32), dim3(32, 8)>>>(X);
    k_mlp_mma<<<dim3(HDIM / 128, NROWS / 128), 256, SMEM_MMA>>>(b1);
    k_gram_mma<<<64, 256, SMEM_GRAM>>>();
    k_solve<<<1, SDIM>>>(w_struct);
    k_final<<<1024, 256>>>(X, out);
}